// round 1
// baseline (speedup 1.0000x reference)
#include <cuda_runtime.h>
#include <cuda_bf16.h>
#include <math.h>

// Problem constants
#define T_STEPS 16
#define BATCH   128
#define IN_DIM  12288
#define H1_DIM  256
#define H2_DIM  512

// Scratch (device globals; no allocation allowed)
__device__ float g_pre1[2048 * 1024];   // [T*B, 4*H1]
__device__ float g_y1  [2048 * 256];    // [T*B, H1]
__device__ float g_pre2[2048 * 2048];   // [T*B, 4*H2]
__device__ float g_h1  [2][128 * 256];  // ping-pong h state, layer 1
__device__ float g_c1  [128 * 256];
__device__ float g_h2  [2][128 * 512];
__device__ float g_c2  [128 * 512];

__device__ __forceinline__ float sigmoidf_(float x) {
    return 1.0f / (1.0f + expf(-x));
}

// ---------------------------------------------------------------------------
// Zero the recurrent states (must run at the start of every graph replay)
// ---------------------------------------------------------------------------
__global__ void zero_states_kernel() {
    int i = blockIdx.x * blockDim.x + threadIdx.x;  // 0 .. 65535
    if (i < 128 * 256) {
        g_h1[0][i] = 0.0f;
        g_c1[i]    = 0.0f;
    }
    if (i < 128 * 512) {
        g_h2[0][i] = 0.0f;
        g_c2[i]    = 0.0f;
    }
}

// ---------------------------------------------------------------------------
// C[m][n] = sum_k A[m][k] * B[n][k] + bias[n]      (NT GEMM, both K-major)
// BM=BN=128, BK=16, 256 threads, 8x8 per thread, register prefetch.
// M, N multiples of 128; K multiple of 16.
// ---------------------------------------------------------------------------
__global__ __launch_bounds__(256) void sgemm_nt_bias(
    int M, int N, int K,
    const float* __restrict__ A,
    const float* __restrict__ B,
    const float* __restrict__ bias,
    float* __restrict__ C)
{
    __shared__ float As[16][128];
    __shared__ float Bs[16][128];

    const int tid = threadIdx.x;
    const int m0 = blockIdx.y * 128;
    const int n0 = blockIdx.x * 128;
    const int ty = tid >> 4;        // 0..15
    const int tx = tid & 15;        // 0..15

    // Load mapping: each thread loads 2 float4 from A and 2 from B per tile
    const int lrow = tid >> 2;      // 0..63
    const int lkq  = tid & 3;       // 0..3  -> k offset lkq*4

    const float* Aptr = A + (long)(m0 + lrow) * K + lkq * 4;
    const float* Bptr = B + (long)(n0 + lrow) * K + lkq * 4;

    float4 pa0 = *(const float4*)(Aptr);
    float4 pa1 = *(const float4*)(Aptr + 64 * (long)K);
    float4 pb0 = *(const float4*)(Bptr);
    float4 pb1 = *(const float4*)(Bptr + 64 * (long)K);

    float acc[8][8];
#pragma unroll
    for (int i = 0; i < 8; i++)
#pragma unroll
        for (int j = 0; j < 8; j++) acc[i][j] = 0.0f;

    for (int kt = 0; kt < K; kt += 16) {
        // store prefetched tile into smem (transposed)
        const int skq = lkq * 4;
        As[skq + 0][lrow] = pa0.x;
        As[skq + 1][lrow] = pa0.y;
        As[skq + 2][lrow] = pa0.z;
        As[skq + 3][lrow] = pa0.w;
        As[skq + 0][lrow + 64] = pa1.x;
        As[skq + 1][lrow + 64] = pa1.y;
        As[skq + 2][lrow + 64] = pa1.z;
        As[skq + 3][lrow + 64] = pa1.w;
        Bs[skq + 0][lrow] = pb0.x;
        Bs[skq + 1][lrow] = pb0.y;
        Bs[skq + 2][lrow] = pb0.z;
        Bs[skq + 3][lrow] = pb0.w;
        Bs[skq + 0][lrow + 64] = pb1.x;
        Bs[skq + 1][lrow + 64] = pb1.y;
        Bs[skq + 2][lrow + 64] = pb1.z;
        Bs[skq + 3][lrow + 64] = pb1.w;
        __syncthreads();

        // prefetch next tile (LDG issued before the long compute section)
        if (kt + 16 < K) {
            Aptr += 16;
            Bptr += 16;
            pa0 = *(const float4*)(Aptr);
            pa1 = *(const float4*)(Aptr + 64 * (long)K);
            pb0 = *(const float4*)(Bptr);
            pb1 = *(const float4*)(Bptr + 64 * (long)K);
        }

#pragma unroll
        for (int k = 0; k < 16; k++) {
            float4 a0 = *(const float4*)(&As[k][ty * 8]);
            float4 a1 = *(const float4*)(&As[k][ty * 8 + 4]);
            float4 b0 = *(const float4*)(&Bs[k][tx * 8]);
            float4 b1 = *(const float4*)(&Bs[k][tx * 8 + 4]);
            float av[8] = {a0.x, a0.y, a0.z, a0.w, a1.x, a1.y, a1.z, a1.w};
            float bv[8] = {b0.x, b0.y, b0.z, b0.w, b1.x, b1.y, b1.z, b1.w};
#pragma unroll
            for (int i = 0; i < 8; i++)
#pragma unroll
                for (int j = 0; j < 8; j++)
                    acc[i][j] = fmaf(av[i], bv[j], acc[i][j]);
        }
        __syncthreads();
    }

    // epilogue: add bias, store
#pragma unroll
    for (int i = 0; i < 8; i++) {
        const int m = m0 + ty * 8 + i;
        float* crow = C + (long)m * N + n0 + tx * 8;
        const float* brow = bias + n0 + tx * 8;
        float4 v0, v1;
        v0.x = acc[i][0] + brow[0];
        v0.y = acc[i][1] + brow[1];
        v0.z = acc[i][2] + brow[2];
        v0.w = acc[i][3] + brow[3];
        v1.x = acc[i][4] + brow[4];
        v1.y = acc[i][5] + brow[5];
        v1.z = acc[i][6] + brow[6];
        v1.w = acc[i][7] + brow[7];
        *(float4*)(crow)     = v0;
        *(float4*)(crow + 4) = v1;
    }
}

// ---------------------------------------------------------------------------
// One LSTM time step (fused recurrent GEMM + gates).
//   gates[b][g*H+j] = pre[b][g*H+j] + sum_k h_in[b][k] * Whh[g*H+j][k]
//   c_new = sig(f)*c + sig(i)*tanh(g);  h_new = sig(o)*tanh(c_new)
// Block: 256 threads = 16 b-rows x 16 j-groups; each thread computes JPT j's
// (all 4 gates each). Grid: (B/16, H/(16*JPT)).
// ---------------------------------------------------------------------------
template <int H, int JPT>
__global__ __launch_bounds__(256) void lstm_step_kernel(
    const float* __restrict__ pre,    // [128][4H] for this t
    const float* __restrict__ Whh,    // [4H][H]
    const float* __restrict__ h_in,   // [128][H]
    float* __restrict__ h_out,        // [128][H]
    float* __restrict__ c,            // [128][H] (in/out)
    float* __restrict__ y)            // [128][H] output for this t
{
    __shared__ float shT[H * 17];     // transposed h tile: shT[k*17 + b_local]

    const int tid = threadIdx.x;
    const int bl  = tid & 15;         // local batch row
    const int jg  = tid >> 4;         // j group 0..15
    const int b0  = blockIdx.x * 16;
    const int jbase = blockIdx.y * (16 * JPT) + jg;

    // load h tile (16 rows x H), transposed into smem
    for (int idx = tid; idx < 16 * H; idx += 256) {
        int bb = idx / H;
        int k  = idx % H;
        shT[k * 17 + bb] = h_in[(b0 + bb) * H + k];
    }
    __syncthreads();

    const float* wp[4 * JPT];
#pragma unroll
    for (int g = 0; g < 4; g++)
#pragma unroll
        for (int p = 0; p < JPT; p++)
            wp[g * JPT + p] = Whh + (long)(g * H + jbase + 16 * p) * H;

    float acc[4 * JPT];
#pragma unroll
    for (int q = 0; q < 4 * JPT; q++) acc[q] = 0.0f;

#pragma unroll 4
    for (int k = 0; k < H; k += 4) {
        const float h0 = shT[(k + 0) * 17 + bl];
        const float h1 = shT[(k + 1) * 17 + bl];
        const float h2 = shT[(k + 2) * 17 + bl];
        const float h3 = shT[(k + 3) * 17 + bl];
#pragma unroll
        for (int q = 0; q < 4 * JPT; q++) {
            float4 w = *(const float4*)(wp[q] + k);
            acc[q] = fmaf(h0, w.x, acc[q]);
            acc[q] = fmaf(h1, w.y, acc[q]);
            acc[q] = fmaf(h2, w.z, acc[q]);
            acc[q] = fmaf(h3, w.w, acc[q]);
        }
    }

    const int b = b0 + bl;
#pragma unroll
    for (int p = 0; p < JPT; p++) {
        const int j = jbase + 16 * p;
        const float ig = acc[0 * JPT + p] + pre[b * 4 * H + 0 * H + j];
        const float fg = acc[1 * JPT + p] + pre[b * 4 * H + 1 * H + j];
        const float gg = acc[2 * JPT + p] + pre[b * 4 * H + 2 * H + j];
        const float og = acc[3 * JPT + p] + pre[b * 4 * H + 3 * H + j];

        const float cold = c[b * H + j];
        const float cn = sigmoidf_(fg) * cold + sigmoidf_(ig) * tanhf(gg);
        const float hn = sigmoidf_(og) * tanhf(cn);

        c[b * H + j]     = cn;
        h_out[b * H + j] = hn;
        y[b * H + j]     = hn;
    }
}

// ---------------------------------------------------------------------------
extern "C" void kernel_launch(void* const* d_in, const int* in_sizes, int n_in,
                              void* d_out, int out_size)
{
    const float* inp  = (const float*)d_in[0];   // [128,16,12288] == flat [2048,12288]
    const float* Wih1 = (const float*)d_in[1];   // [1024,12288]
    const float* Whh1 = (const float*)d_in[2];   // [1024,256]
    const float* b1   = (const float*)d_in[3];   // [1024]
    const float* Wih2 = (const float*)d_in[4];   // [2048,256]
    const float* Whh2 = (const float*)d_in[5];   // [2048,512]
    const float* b2   = (const float*)d_in[6];   // [2048]
    float* out = (float*)d_out;                  // [16,128,512] flat == [128, 8192]

    float *pre1, *y1, *pre2, *h1, *c1, *h2, *c2;
    cudaGetSymbolAddress((void**)&pre1, g_pre1);
    cudaGetSymbolAddress((void**)&y1,   g_y1);
    cudaGetSymbolAddress((void**)&pre2, g_pre2);
    cudaGetSymbolAddress((void**)&h1,   g_h1);
    cudaGetSymbolAddress((void**)&c1,   g_c1);
    cudaGetSymbolAddress((void**)&h2,   g_h2);
    cudaGetSymbolAddress((void**)&c2,   g_c2);

    // 0) zero recurrent states (graph replays need fresh state every time)
    zero_states_kernel<<<256, 256>>>();

    // 1) layer-1 input projection: pre1[2048,1024] = X @ Wih1^T + b1
    sgemm_nt_bias<<<dim3(1024 / 128, 2048 / 128), 256>>>(
        2048, 1024, IN_DIM, inp, Wih1, b1, pre1);

    // 2) layer-1 recurrence
    for (int t = 0; t < T_STEPS; t++) {
        lstm_step_kernel<H1_DIM, 1><<<dim3(8, 16), 256>>>(
            pre1 + t * (BATCH * 4 * H1_DIM), Whh1,
            h1 + (t & 1) * (BATCH * H1_DIM),
            h1 + ((t + 1) & 1) * (BATCH * H1_DIM),
            c1,
            y1 + t * (BATCH * H1_DIM));
    }

    // 3) layer-2 input projection: pre2[2048,2048] = Y1 @ Wih2^T + b2
    sgemm_nt_bias<<<dim3(2048 / 128, 2048 / 128), 256>>>(
        2048, 2048, H1_DIM, y1, Wih2, b2, pre2);

    // 4) layer-2 recurrence, writing h directly into d_out ([T,B,H2] flat)
    for (int t = 0; t < T_STEPS; t++) {
        lstm_step_kernel<H2_DIM, 2><<<dim3(8, 16), 256>>>(
            pre2 + t * (BATCH * 4 * H2_DIM), Whh2,
            h2 + (t & 1) * (BATCH * H2_DIM),
            h2 + ((t + 1) & 1) * (BATCH * H2_DIM),
            c2,
            out + t * (BATCH * H2_DIM));
    }
}

// round 5
// speedup vs baseline: 2.0481x; 2.0481x over previous
#include <cuda_runtime.h>
#include <cuda_bf16.h>
#include <math.h>
#include <stdint.h>

// Problem constants
#define T_STEPS 16
#define BATCH   128
#define IN_DIM  12288
#define H1_DIM  256
#define H2_DIM  512

// ---------------------------------------------------------------------------
// Device-global scratch (no allocation allowed)
// ---------------------------------------------------------------------------
__device__ __align__(256) __nv_bfloat16 g_Xhi [2048 * 12288];
__device__ __align__(256) __nv_bfloat16 g_Xlo [2048 * 12288];
__device__ __align__(256) __nv_bfloat16 g_W1hi[1024 * 12288];
__device__ __align__(256) __nv_bfloat16 g_W1lo[1024 * 12288];
__device__ __align__(256) __nv_bfloat16 g_W2hi[2048 * 256];
__device__ __align__(256) __nv_bfloat16 g_W2lo[2048 * 256];
__device__ __align__(256) __nv_bfloat16 g_y1hi[2048 * 256];
__device__ __align__(256) __nv_bfloat16 g_y1lo[2048 * 256];

__device__ float g_pre1 [2048 * 1024];    // [T*B, 4*H1]
__device__ float g_pre2 [2048 * 2048];    // [T*B, 4*H2]
__device__ float g_part1[4 * 128 * 1024]; // k-split partials layer 1
__device__ float g_part2[4 * 128 * 2048]; // k-split partials layer 2
__device__ float g_h1[2][128 * 256];
__device__ float g_c1[128 * 256];
__device__ float g_h2[2][128 * 512];
__device__ float g_c2[128 * 512];

__device__ __forceinline__ float sigmoidf_(float x) {
    return 1.0f / (1.0f + expf(-x));
}

// ---------------------------------------------------------------------------
// PTX helpers (compute_103-safe: cp.async + ldmatrix + mma.sync only)
// ---------------------------------------------------------------------------
__device__ __forceinline__ uint32_t smem_u32(const void* p) {
    uint32_t a;
    asm("{ .reg .u64 t; cvta.to.shared.u64 t, %1; cvt.u32.u64 %0, t; }"
        : "=r"(a) : "l"(p));
    return a;
}

template <int N>
__device__ __forceinline__ void cpwait() {
    asm volatile("cp.async.wait_group %0;" :: "n"(N));
}

__device__ __forceinline__ void cp16(uint32_t dst, const void* src) {
    asm volatile("cp.async.cg.shared.global [%0], [%1], 16;"
                 :: "r"(dst), "l"(src));
}

__device__ __forceinline__ void cpcommit() {
    asm volatile("cp.async.commit_group;");
}

__device__ __forceinline__ void ldsm4(uint32_t* r, uint32_t addr) {
    asm volatile("ldmatrix.sync.aligned.m8n8.x4.shared.b16 {%0,%1,%2,%3}, [%4];"
                 : "=r"(r[0]), "=r"(r[1]), "=r"(r[2]), "=r"(r[3]) : "r"(addr));
}

__device__ __forceinline__ void mma_bf16(float* d, const uint32_t* a,
                                         uint32_t b0, uint32_t b1) {
    asm volatile(
        "mma.sync.aligned.m16n8k16.row.col.f32.bf16.bf16.f32 "
        "{%0,%1,%2,%3}, {%4,%5,%6,%7}, {%8,%9}, {%0,%1,%2,%3};"
        : "+f"(d[0]), "+f"(d[1]), "+f"(d[2]), "+f"(d[3])
        : "r"(a[0]), "r"(a[1]), "r"(a[2]), "r"(a[3]), "r"(b0), "r"(b1));
}

// ---------------------------------------------------------------------------
// Zero the recurrent states
// ---------------------------------------------------------------------------
__global__ void zero_states_kernel() {
    int i = blockIdx.x * blockDim.x + threadIdx.x;
    if (i < 128 * 256) { g_h1[0][i] = 0.0f; g_c1[i] = 0.0f; }
    if (i < 128 * 512) { g_h2[0][i] = 0.0f; g_c2[i] = 0.0f; }
}

// ---------------------------------------------------------------------------
// fp32 -> (hi, lo) bf16 split
// ---------------------------------------------------------------------------
__global__ void split_kernel(const float* __restrict__ x,
                             __nv_bfloat16* __restrict__ hi,
                             __nv_bfloat16* __restrict__ lo, int n4) {
    int i = blockIdx.x * blockDim.x + threadIdx.x;
    if (i >= n4) return;
    float4 v = ((const float4*)x)[i];
    __nv_bfloat16 h0 = __float2bfloat16(v.x);
    __nv_bfloat16 h1 = __float2bfloat16(v.y);
    __nv_bfloat16 h2 = __float2bfloat16(v.z);
    __nv_bfloat16 h3 = __float2bfloat16(v.w);
    __nv_bfloat16 l0 = __float2bfloat16(v.x - __bfloat162float(h0));
    __nv_bfloat16 l1 = __float2bfloat16(v.y - __bfloat162float(h1));
    __nv_bfloat16 l2 = __float2bfloat16(v.z - __bfloat162float(h2));
    __nv_bfloat16 l3 = __float2bfloat16(v.w - __bfloat162float(h3));
    ((__nv_bfloat162*)hi)[i * 2 + 0] = __nv_bfloat162(h0, h1);
    ((__nv_bfloat162*)hi)[i * 2 + 1] = __nv_bfloat162(h2, h3);
    ((__nv_bfloat162*)lo)[i * 2 + 0] = __nv_bfloat162(l0, l1);
    ((__nv_bfloat162*)lo)[i * 2 + 1] = __nv_bfloat162(l2, l3);
}

// ---------------------------------------------------------------------------
// Split-bf16 HMMA GEMM: C[m][n] = sum_k A[m][k]*B[n][k]  (fp32 accum/result)
// A = Ahi+Alo, B = Bhi+Blo; accumulate hi*hi + hi*lo + lo*hi.
// Tile 128x128x32, 3-stage cp.async pipeline, 256 threads (8 warps, 2x4),
// warp tile 64x32, mma.sync.m16n8k16.bf16. grid = (N/128, M/128).
// ---------------------------------------------------------------------------
#define GSTAGES 3
#define TILE_B 8192                       // one 128x32 bf16 tile
#define GSTAGE_BYTES (4 * TILE_B)         // Ah, Al, Bh, Bl
#define GSMEM_TOTAL (GSTAGES * GSTAGE_BYTES)

// swizzled offset of (row, chunk) within an 8KB tile; chunk = 16B = 8 bf16
__device__ __forceinline__ uint32_t swz(int row, int c) {
    return (uint32_t)(row * 64 + 16 * (c ^ ((row >> 1) & 3)));
}

__global__ __launch_bounds__(256) void gemm_bf16split(
    const __nv_bfloat16* __restrict__ Ahi, const __nv_bfloat16* __restrict__ Alo,
    const __nv_bfloat16* __restrict__ Bhi, const __nv_bfloat16* __restrict__ Blo,
    float* __restrict__ C, int N, int K)
{
    extern __shared__ __align__(1024) char gsm[];
    const uint32_t sbase = smem_u32(gsm);
    const int tid = threadIdx.x;
    const int wid = tid >> 5;
    const int lane = tid & 31;
    const int m0 = blockIdx.y * 128;
    const int n0 = blockIdx.x * 128;
    const int NK = K >> 5;                // 32-wide K chunks

    const int wm = (wid & 1) * 64;        // warp m offset in tile
    const int wn = (wid >> 1) * 32;       // warp n offset in tile

    // loader: one 32-elem K chunk = 4 tiles of [128 x 32 bf16]
    auto load_chunk = [&](int ko, int s) {
        const uint32_t stg = sbase + s * GSTAGE_BYTES;
        const int k0 = ko * 32;
#pragma unroll
        for (int it = 0; it < 8; it++) {
            int flat = tid + it * 256;        // 0..2047
            int tile = flat >> 9;             // 0..3
            int within = flat & 511;
            int row = within >> 2;            // 0..127
            int c = within & 3;               // 16B chunk
            const __nv_bfloat16* gp;
            if (tile == 0)      gp = Ahi + (long)(m0 + row) * K + k0 + c * 8;
            else if (tile == 1) gp = Alo + (long)(m0 + row) * K + k0 + c * 8;
            else if (tile == 2) gp = Bhi + (long)(n0 + row) * K + k0 + c * 8;
            else                gp = Blo + (long)(n0 + row) * K + k0 + c * 8;
            cp16(stg + tile * TILE_B + swz(row, c), gp);
        }
        cpcommit();
    };

    const int npre = (NK < GSTAGES) ? NK : GSTAGES;
    for (int k = 0; k < npre; k++) load_chunk(k, k);

    float acc[4][4][4];
#pragma unroll
    for (int i = 0; i < 4; i++)
#pragma unroll
        for (int j = 0; j < 4; j++)
#pragma unroll
            for (int q = 0; q < 4; q++) acc[i][j][q] = 0.0f;

    // ldmatrix lane addressing (constant per thread)
    // A .x4: lanes 0-7 -> (m 0-7, klo), 8-15 -> (m 8-15, klo),
    //        16-23 -> (m 0-7, khi), 24-31 -> (m 8-15, khi)
    const int a_row_off = ((lane >> 3) & 1) * 8 + (lane & 7);
    const int a_k_off = (lane >> 4);              // 0: k+0..7, 1: k+8..15
    // B .x4: lanes (n-octet = lane/8) rows wn+lane, fixed chunk
    const int b_row = wn + lane;

    for (int k = 0; k < NK; k++) {
        const int s = k % GSTAGES;
        const int rem = NK - 1 - k;
        if (rem >= GSTAGES - 1)      cpwait<GSTAGES - 1>();
        else if (rem == 1)           cpwait<1>();
        else                         cpwait<0>();
        __syncthreads();

        const uint32_t stg = sbase + s * GSTAGE_BYTES;
        const uint32_t ah = stg;
        const uint32_t al = stg + TILE_B;
        const uint32_t bh = stg + 2 * TILE_B;
        const uint32_t bl = stg + 3 * TILE_B;

#pragma unroll
        for (int ks = 0; ks < 2; ks++) {          // two k16 slices per chunk
            const int kc = ks * 2;                // base 16B chunk of slice
            uint32_t Ah[4][4], Al[4][4];
            uint32_t Bh0[4], Bh1[4], Bl0[4], Bl1[4];
#pragma unroll
            for (int mt = 0; mt < 4; mt++) {
                const int r = wm + mt * 16 + a_row_off;
                ldsm4(Ah[mt], ah + swz(r, kc + a_k_off));
                ldsm4(Al[mt], al + swz(r, kc + a_k_off));
            }
            ldsm4(Bh0, bh + swz(b_row, kc));
            ldsm4(Bh1, bh + swz(b_row, kc + 1));
            ldsm4(Bl0, bl + swz(b_row, kc));
            ldsm4(Bl1, bl + swz(b_row, kc + 1));
#pragma unroll
            for (int mt = 0; mt < 4; mt++) {
#pragma unroll
                for (int nt = 0; nt < 4; nt++) {
                    mma_bf16(acc[mt][nt], Ah[mt], Bh0[nt], Bh1[nt]);
                    mma_bf16(acc[mt][nt], Ah[mt], Bl0[nt], Bl1[nt]);
                    mma_bf16(acc[mt][nt], Al[mt], Bh0[nt], Bh1[nt]);
                }
            }
        }
        __syncthreads();
        if (k + GSTAGES < NK) load_chunk(k + GSTAGES, s);
    }

    // epilogue: registers -> gmem (float2 stores)
#pragma unroll
    for (int mt = 0; mt < 4; mt++) {
#pragma unroll
        for (int nt = 0; nt < 4; nt++) {
            const int row = m0 + wm + mt * 16 + (lane >> 2);
            const int col = n0 + wn + nt * 8 + (lane & 3) * 2;
            float2 v0 = make_float2(acc[mt][nt][0], acc[mt][nt][1]);
            float2 v1 = make_float2(acc[mt][nt][2], acc[mt][nt][3]);
            *(float2*)&C[(long)row * N + col] = v0;
            *(float2*)&C[(long)(row + 8) * N + col] = v1;
        }
    }
}

// ---------------------------------------------------------------------------
// Phase A: partial recurrent matvec with k-split.
//   part[kz][b][g*H+j] = sum_{k in chunk kz} h_in[b][k] * Whh[g*H+j][k]
// grid (B/16, H/(16*JPT), 4), 256 threads.
// ---------------------------------------------------------------------------
template <int H, int JPT, int KS>
__global__ __launch_bounds__(256) void lstm_partial(
    const float* __restrict__ Whh,
    const float* __restrict__ h_in,
    float* __restrict__ part)
{
    __shared__ float shT[KS * 17];

    const int tid = threadIdx.x;
    const int bl = tid & 15;
    const int jg = tid >> 4;
    const int b0 = blockIdx.x * 16;
    const int jbase = blockIdx.y * (16 * JPT) + jg;
    const int kz = blockIdx.z;
    const int k0 = kz * KS;

    for (int idx = tid; idx < 16 * KS; idx += 256) {
        int bb = idx / KS;
        int k = idx % KS;
        shT[k * 17 + bb] = h_in[(b0 + bb) * H + k0 + k];
    }
    __syncthreads();

    const float* wp[4 * JPT];
#pragma unroll
    for (int g = 0; g < 4; g++)
#pragma unroll
        for (int p = 0; p < JPT; p++)
            wp[g * JPT + p] = Whh + (long)(g * H + jbase + 16 * p) * H + k0;

    float acc[4 * JPT];
#pragma unroll
    for (int q = 0; q < 4 * JPT; q++) acc[q] = 0.0f;

#pragma unroll 4
    for (int k = 0; k < KS; k += 4) {
        const float h0 = shT[(k + 0) * 17 + bl];
        const float h1 = shT[(k + 1) * 17 + bl];
        const float h2 = shT[(k + 2) * 17 + bl];
        const float h3 = shT[(k + 3) * 17 + bl];
#pragma unroll
        for (int q = 0; q < 4 * JPT; q++) {
            float4 w = *(const float4*)(wp[q] + k);
            acc[q] = fmaf(h0, w.x, acc[q]);
            acc[q] = fmaf(h1, w.y, acc[q]);
            acc[q] = fmaf(h2, w.z, acc[q]);
            acc[q] = fmaf(h3, w.w, acc[q]);
        }
    }

    const int b = b0 + bl;
    float* pp = part + (long)kz * BATCH * 4 * H + (long)b * 4 * H;
#pragma unroll
    for (int g = 0; g < 4; g++)
#pragma unroll
        for (int p = 0; p < JPT; p++)
            pp[g * H + jbase + 16 * p] = acc[g * JPT + p];
}

// ---------------------------------------------------------------------------
// Phase B: combine partials + pre + bias, apply gate nonlinearity.
// One thread per (b, j). grid = B*H/256.
// ---------------------------------------------------------------------------
template <int H, bool WRITE_BF16>
__global__ __launch_bounds__(256) void lstm_gates(
    const float* __restrict__ pre,     // [B][4H] slice for this t
    const float* __restrict__ part,    // [4][B][4H]
    const float* __restrict__ bias,    // [4H]
    float* __restrict__ c,             // [B][H]
    float* __restrict__ h_out,         // [B][H]
    float* __restrict__ y_f32,         // layer2: output slice
    __nv_bfloat16* __restrict__ yhi,   // layer1: bf16 hi slice
    __nv_bfloat16* __restrict__ ylo)   // layer1: bf16 lo slice
{
    const int idx = blockIdx.x * 256 + threadIdx.x;   // b*H + j
    const int b = idx / H;
    const int j = idx % H;

    float gate[4];
#pragma unroll
    for (int g = 0; g < 4; g++) {
        const int o = b * 4 * H + g * H + j;
        float v = pre[o] + bias[g * H + j];
        v += part[0 * BATCH * 4 * H + o];
        v += part[1 * BATCH * 4 * H + o];
        v += part[2 * BATCH * 4 * H + o];
        v += part[3 * BATCH * 4 * H + o];
        gate[g] = v;
    }

    const float cold = c[idx];
    const float cn = sigmoidf_(gate[1]) * cold + sigmoidf_(gate[0]) * tanhf(gate[2]);
    const float hn = sigmoidf_(gate[3]) * tanhf(cn);

    c[idx] = cn;
    h_out[idx] = hn;
    if (WRITE_BF16) {
        __nv_bfloat16 hi = __float2bfloat16(hn);
        yhi[idx] = hi;
        ylo[idx] = __float2bfloat16(hn - __bfloat162float(hi));
    } else {
        y_f32[idx] = hn;
    }
}

// ---------------------------------------------------------------------------
extern "C" void kernel_launch(void* const* d_in, const int* in_sizes, int n_in,
                              void* d_out, int out_size)
{
    const float* inp  = (const float*)d_in[0];   // [128,16,12288] flat [2048,12288]
    const float* Wih1 = (const float*)d_in[1];   // [1024,12288]
    const float* Whh1 = (const float*)d_in[2];   // [1024,256]
    const float* b1   = (const float*)d_in[3];   // [1024]
    const float* Wih2 = (const float*)d_in[4];   // [2048,256]
    const float* Whh2 = (const float*)d_in[5];   // [2048,512]
    const float* b2   = (const float*)d_in[6];   // [2048]
    float* out = (float*)d_out;                  // [16,128,512] flat

    __nv_bfloat16 *Xhi, *Xlo, *W1hi, *W1lo, *W2hi, *W2lo, *y1hi, *y1lo;
    float *pre1, *pre2, *part1, *part2, *h1, *c1, *h2, *c2;
    cudaGetSymbolAddress((void**)&Xhi,  g_Xhi);
    cudaGetSymbolAddress((void**)&Xlo,  g_Xlo);
    cudaGetSymbolAddress((void**)&W1hi, g_W1hi);
    cudaGetSymbolAddress((void**)&W1lo, g_W1lo);
    cudaGetSymbolAddress((void**)&W2hi, g_W2hi);
    cudaGetSymbolAddress((void**)&W2lo, g_W2lo);
    cudaGetSymbolAddress((void**)&y1hi, g_y1hi);
    cudaGetSymbolAddress((void**)&y1lo, g_y1lo);
    cudaGetSymbolAddress((void**)&pre1, g_pre1);
    cudaGetSymbolAddress((void**)&pre2, g_pre2);
    cudaGetSymbolAddress((void**)&part1, g_part1);
    cudaGetSymbolAddress((void**)&part2, g_part2);
    cudaGetSymbolAddress((void**)&h1, g_h1);
    cudaGetSymbolAddress((void**)&c1, g_c1);
    cudaGetSymbolAddress((void**)&h2, g_h2);
    cudaGetSymbolAddress((void**)&c2, g_c2);

    cudaFuncSetAttribute(gemm_bf16split,
                         cudaFuncAttributeMaxDynamicSharedMemorySize, GSMEM_TOTAL);

    // 0) fresh recurrent state
    zero_states_kernel<<<256, 256>>>();

    // 1) bf16 hi/lo splits of X, W1, W2
    split_kernel<<<(2048 * 12288 / 4 + 255) / 256, 256>>>(inp,  Xhi,  Xlo,  2048 * 12288 / 4);
    split_kernel<<<(1024 * 12288 / 4 + 255) / 256, 256>>>(Wih1, W1hi, W1lo, 1024 * 12288 / 4);
    split_kernel<<<(2048 * 256 / 4 + 255) / 256, 256>>>(Wih2, W2hi, W2lo, 2048 * 256 / 4);

    // 2) layer-1 input projection (HMMA): pre1[2048,1024]
    gemm_bf16split<<<dim3(1024 / 128, 2048 / 128), 256, GSMEM_TOTAL>>>(
        Xhi, Xlo, W1hi, W1lo, pre1, 1024, IN_DIM);

    // 3) layer-1 recurrence
    for (int t = 0; t < T_STEPS; t++) {
        lstm_partial<H1_DIM, 1, 64><<<dim3(8, 16, 4), 256>>>(
            Whh1, h1 + (t & 1) * (BATCH * H1_DIM), part1);
        lstm_gates<H1_DIM, true><<<BATCH * H1_DIM / 256, 256>>>(
            pre1 + t * (BATCH * 4 * H1_DIM), part1, b1,
            c1, h1 + ((t + 1) & 1) * (BATCH * H1_DIM),
            nullptr,
            y1hi + t * (BATCH * H1_DIM), y1lo + t * (BATCH * H1_DIM));
    }

    // 4) layer-2 input projection (HMMA): pre2[2048,2048]
    gemm_bf16split<<<dim3(2048 / 128, 2048 / 128), 256, GSMEM_TOTAL>>>(
        y1hi, y1lo, W2hi, W2lo, pre2, 2048, H1_DIM);

    // 5) layer-2 recurrence -> d_out
    for (int t = 0; t < T_STEPS; t++) {
        lstm_partial<H2_DIM, 2, 128><<<dim3(8, 16, 4), 256>>>(
            Whh2, h2 + (t & 1) * (BATCH * H2_DIM), part2);
        lstm_gates<H2_DIM, false><<<BATCH * H2_DIM / 256, 256>>>(
            pre2 + t * (BATCH * 4 * H2_DIM), part2, b2,
            c2, h2 + ((t + 1) & 1) * (BATCH * H2_DIM),
            out + t * (BATCH * H2_DIM),
            nullptr, nullptr);
    }
}